// round 15
// baseline (speedup 1.0000x reference)
#include <cuda_runtime.h>

// ---------------- problem constants (fixed by dataset) ----------------
#define NPIX 147456        // 384*384
#define W384 384
#define NNZC 1474560       // NPIX/2 * 20
#define NLOC 73728         // NPIX/2
#define KIU  5
#define CG_STEPS 30

#define TPB   512
#define NBLK  288          // 288*512 == NPIX exactly
#define MPB   256          // matting pixels per block (NLOC / NBLK)
#define NWARP (TPB / 32)

// ---------------- device scratch (static only) ----------------
__device__ int2  g_pairR[NNZC];        // CSR-sorted {col, val-bits}
__device__ int   g_ptrR[NPIX + 1];
__device__ int   g_ptrM[NPIX];
__device__ int   g_ptrI[NPIX];
__device__ int   g_cntR[NPIX];
__device__ int   g_cntM[NPIX];
__device__ int   g_cntI[NPIX];
__device__ int   g_tmpR[NPIX];
__device__ int   g_tmpM[NPIX];
__device__ int   g_tmpI[NPIX];
__device__ int   g_btot[432];
__device__ int   g_boff[432];

__device__ int   g_mInd[NLOC];         // matting pixel indices, sorted ascending
__device__ int   g_iInd[NLOC];         // IU pixel indices, sorted ascending
__device__ float g_rs_cm[NPIX];
__device__ float g_D[NPIX];
__device__ float g_S45[45 * NLOC];     // symmetric matting blocks [t*NLOC + sorted_pos]
__device__ float g_Wiu[KIU * NLOC];    // [l*NLOC + sorted_pos]
__device__ int   g_iuNbT[KIU * NLOC];  // [l*NLOC + sorted_pos]
__device__ float g_r[NPIX];
__device__ float g_w[NPIX];            // A*r accumulator (atomic; zeroed each iter)
__device__ double2 g_dot1[NBLK];       // {gamma, delta} partials

__device__ unsigned g_count;
__device__ volatile unsigned g_sense;

// ---------------- helpers ----------------
__device__ __forceinline__ int OFF9(int i) {
    int a = i / 3, b = i % 3;
    return (a - 1) + (b - 1) * W384;
}
__device__ __forceinline__ int TIDX(int i, int j) {
    return 9 * i - (i * (i - 1)) / 2 + (j - i);
}

__device__ __forceinline__ double2 bred2(double a, double b, double2* sm2) {
    int lane = threadIdx.x & 31, w = threadIdx.x >> 5;
    #pragma unroll
    for (int o = 16; o > 0; o >>= 1) {
        a += __shfl_down_sync(0xffffffffu, a, o);
        b += __shfl_down_sync(0xffffffffu, b, o);
    }
    if (lane == 0) sm2[w] = make_double2(a, b);
    __syncthreads();
    if (w == 0) {
        double2 t = (lane < NWARP) ? sm2[lane] : make_double2(0.0, 0.0);
        a = t.x; b = t.y;
        #pragma unroll
        for (int o = 8; o > 0; o >>= 1) {
            a += __shfl_down_sync(0xffffu, a, o);
            b += __shfl_down_sync(0xffffu, b, o);
        }
    }
    __syncthreads();
    return make_double2(a, b);
}

__device__ __forceinline__ void gbar(unsigned &ep) {
    ep++;
    __syncthreads();
    if (threadIdx.x == 0) {
        __threadfence();
        if (atomicAdd(&g_count, 1u) == NBLK - 1) {
            g_count = 0;
            __threadfence();
            g_sense = ep;
        } else {
            while (g_sense != ep) { __nanosleep(32); }
            __threadfence();
        }
    }
    __syncthreads();
}

// ---------------- setup kernels ----------------
__global__ void k_z() {
    int i = blockIdx.x * blockDim.x + threadIdx.x;
    if (i < NPIX) {
        g_cntR[i] = 0; g_cntM[i] = 0; g_cntI[i] = 0;
        g_tmpR[i] = 0; g_tmpM[i] = 0; g_tmpI[i] = 0;
        g_rs_cm[i] = 0.f; g_D[i] = 0.f; g_w[i] = 0.f;
    }
    if (i == 0) { g_count = 0; g_sense = 0; }
}

__global__ void k_cnt(const float* __restrict__ CMw, const float* __restrict__ Wd,
                      const int* __restrict__ row,
                      const int* __restrict__ locInd, const int* __restrict__ iuInd) {
    int k = blockIdx.x * blockDim.x + threadIdx.x;
    if (k < NLOC) {
        atomicAdd(&g_cntM[locInd[k]], 1);
        atomicAdd(&g_cntI[iuInd[k]], 1);
    }
    if (k >= NNZC) return;
    int r = row[k];
    float cv = CMw[r] * Wd[k];
    atomicAdd(&g_rs_cm[r], cv);
    atomicAdd(&g_cntR[r], 1);
}

// 432 blocks x 1024: segments of 144 blocks scan cntR / cntM / cntI
__global__ void k_scanA() {
    __shared__ int sm[1024];
    int seg = blockIdx.x / 144;
    int blk = blockIdx.x % 144;
    int gi  = blk * 1024 + threadIdx.x;
    int* cnt = (seg == 0) ? g_cntR : (seg == 1) ? g_cntM : g_cntI;
    int* ptr = (seg == 0) ? g_ptrR : (seg == 1) ? g_ptrM : g_ptrI;
    int v = cnt[gi];
    sm[threadIdx.x] = v;
    __syncthreads();
    for (int o = 1; o < 1024; o <<= 1) {
        int t = (threadIdx.x >= o) ? sm[threadIdx.x - o] : 0;
        __syncthreads();
        sm[threadIdx.x] += t;
        __syncthreads();
    }
    ptr[gi] = sm[threadIdx.x] - v;
    if (threadIdx.x == 1023) g_btot[blockIdx.x] = sm[1023];
}

__global__ void k_scanB() {
    __shared__ int sm[432];
    int t = threadIdx.x;
    int v = (t < 432) ? g_btot[t] : 0;
    if (t < 432) sm[t] = v;
    __syncthreads();
    for (int o = 1; o < 432; o <<= 1) {
        int add = 0;
        if (t < 432 && t >= o) add = sm[t - o];
        __syncthreads();
        if (t < 432) sm[t] += add;
        __syncthreads();
    }
    if (t < 432) {
        int ex = sm[t] - v;
        int seg = t / 144;
        int base = (seg > 0) ? sm[seg * 144 - 1] : 0;
        g_boff[t] = ex - base;
    }
}

__global__ void k_scanC() {
    int seg = blockIdx.x / 144;
    int blk = blockIdx.x % 144;
    int gi  = blk * 1024 + threadIdx.x;
    int* ptr = (seg == 0) ? g_ptrR : (seg == 1) ? g_ptrM : g_ptrI;
    ptr[gi] += g_boff[blockIdx.x];
    if (blockIdx.x == 0 && threadIdx.x == 0) g_ptrR[NPIX] = NNZC;
}

__global__ void k_scatter(const float* __restrict__ CMw, const float* __restrict__ Wd,
                          const int* __restrict__ row, const int* __restrict__ col) {
    int k = blockIdx.x * blockDim.x + threadIdx.x;
    if (k >= NNZC) return;
    int r = row[k], c = col[k];
    int vb = __float_as_int(CMw[r] * Wd[k]);
    int p1 = g_ptrR[r] + atomicAdd(&g_tmpR[r], 1);
    g_pairR[p1] = make_int2(c, vb);
}

// symmetric matting blocks written at SORTED positions
__global__ void k_p2(const float* __restrict__ LOCw, const float* __restrict__ LF,
                     const int* __restrict__ inInd) {
    int m0 = blockIdx.x * blockDim.x + threadIdx.x;
    if (m0 >= NLOC) return;
    int ind = inInd[m0];
    int pos = g_ptrM[ind] + atomicAdd(&g_tmpM[ind], 1);
    g_mInd[pos] = ind;
    float w = LOCw[ind];
    float rs[9];
    #pragma unroll
    for (int q = 0; q < 9; q++) rs[q] = 0.f;
    #pragma unroll
    for (int a = 0; a < 9; a++) {
        #pragma unroll
        for (int b2 = a; b2 < 9; b2++) {
            float s = 0.5f * w * (LF[(b2 * 9 + a) * NLOC + m0] + LF[(a * 9 + b2) * NLOC + m0]);
            g_S45[TIDX(a, b2) * NLOC + pos] = s;
            rs[a] += s;
            if (b2 > a) rs[b2] += s;
        }
    }
    #pragma unroll
    for (int q = 0; q < 9; q++) atomicAdd(&g_D[ind + OFF9(q)], rs[q]);
}

// IU weights written at SORTED positions
__global__ void k_p3(const float* __restrict__ IUw, const float* __restrict__ IUf,
                     const int* __restrict__ inInd, const int* __restrict__ nbInd) {
    int k = blockIdx.x * blockDim.x + threadIdx.x;
    if (k >= NLOC) return;
    int ind = inInd[k];
    int pos = g_ptrI[ind] + atomicAdd(&g_tmpI[ind], 1);
    g_iInd[pos] = ind;
    float w = IUw[ind];
    #pragma unroll
    for (int l = 0; l < KIU; l++) {
        float wv = 0.5f * w * IUf[k * KIU + l];
        int nb = nbInd[k * KIU + l];
        g_Wiu[l * NLOC + pos] = wv;
        g_iuNbT[l * NLOC + pos] = nb;
        atomicAdd(&g_D[ind], wv);
        atomicAdd(&g_D[nb], wv);
    }
}

__global__ void k_p4(const float* __restrict__ KUw, const float* __restrict__ kToUconf,
                     const float* __restrict__ known, const float* __restrict__ kToU,
                     const float* __restrict__ lmbda, float* __restrict__ x) {
    int i = blockIdx.x * blockDim.x + threadIdx.x;
    if (i >= NPIX) return;
    float dk = KUw[i] * kToUconf[i] + lmbda[0] * known[i];
    float b  = dk * kToU[i];
    g_D[i] += dk;
    g_r[i] = b;     // r0 = b (x0 = 0)
    x[i] = 0.f;
}

// ---------------- persistent single-reduction CG kernel ----------------
// Per iteration: ONE matvec phase (gather + register-Lv scatter + matting + IU),
// ONE update phase. delta uses r.(A r) = sum(Lv^2) + sum(D r^2) + matting + IU.
__global__ void __launch_bounds__(TPB, 2) k_cg(float* __restrict__ x)
{
    __shared__ double2 sm2[NWARP];
    __shared__ double s_alpha, s_beta, s_gamma_prev, s_alpha_prev;
    const int tid  = threadIdx.x;
    const int gtid = blockIdx.x * TPB + tid;     // always < NPIX
    const int m    = blockIdx.x * MPB + tid;     // sorted matting/IU slot if tid < MPB
    unsigned ep = 0;

    float r_reg = g_r[gtid];
    float p_reg = 0.f, s_reg = 0.f;
    const float rc = g_rs_cm[gtid];
    const float Di = g_D[gtid];
    const int rb0 = g_ptrR[gtid], rb1 = g_ptrR[gtid + 1];

    for (int it = 0; it < CG_STEPS; ++it) {
        // ---- Phase A: full matvec in one phase
        {
            // pass 1: gather r over CSR row -> Lv (register); pairs cache in L1
            float acc = 0.f;
            int k = rb0;
            for (; k + 4 <= rb1; k += 4) {
                int2 e0 = g_pairR[k],     e1 = g_pairR[k + 1];
                int2 e2 = g_pairR[k + 2], e3 = g_pairR[k + 3];
                acc += __int_as_float(e0.y) * g_r[e0.x]
                     + __int_as_float(e1.y) * g_r[e1.x]
                     + __int_as_float(e2.y) * g_r[e2.x]
                     + __int_as_float(e3.y) * g_r[e3.x];
            }
            for (; k < rb1; k++) {
                int2 e = g_pairR[k];
                acc += __int_as_float(e.y) * g_r[e.x];
            }
            float lv = rc * r_reg - acc;
            float wi = rc * lv + Di * r_reg;
            atomicAdd(&g_w[gtid], wi);
            double dD = (double)lv * (double)lv + (double)(Di * r_reg) * (double)r_reg;

            // pass 2: scatter -val*lv to w[col] (L1-hot pair re-read)
            for (k = rb0; k + 4 <= rb1; k += 4) {
                int2 e0 = g_pairR[k],     e1 = g_pairR[k + 1];
                int2 e2 = g_pairR[k + 2], e3 = g_pairR[k + 3];
                atomicAdd(&g_w[e0.x], -__int_as_float(e0.y) * lv);
                atomicAdd(&g_w[e1.x], -__int_as_float(e1.y) * lv);
                atomicAdd(&g_w[e2.x], -__int_as_float(e2.y) * lv);
                atomicAdd(&g_w[e3.x], -__int_as_float(e3.y) * lv);
            }
            for (; k < rb1; k++) {
                int2 e = g_pairR[k];
                atomicAdd(&g_w[e.x], -__int_as_float(e.y) * lv);
            }

            // matting (sorted; needs only r)
            if (tid < MPB) {
                int ind = g_mInd[m];
                float pn[9], acc9[9];
                #pragma unroll
                for (int j = 0; j < 9; j++) { pn[j] = g_r[ind + OFF9(j)]; acc9[j] = 0.f; }
                #pragma unroll
                for (int i9 = 0; i9 < 9; i9++) {
                    #pragma unroll
                    for (int j9 = i9; j9 < 9; j9++) {
                        float v = g_S45[TIDX(i9, j9) * NLOC + m];
                        acc9[i9] += v * pn[j9];
                        if (j9 > i9) acc9[j9] += v * pn[i9];
                    }
                }
                #pragma unroll
                for (int i9 = 0; i9 < 9; i9++) {
                    atomicAdd(&g_w[ind + OFF9(i9)], -acc9[i9]);
                    dD -= (double)acc9[i9] * (double)pn[i9];
                }
                // IU KNN (sorted by owning pixel)
                int ind2 = g_iInd[m];
                float rind = g_r[ind2];
                float acc2 = 0.f;
                #pragma unroll
                for (int l = 0; l < KIU; l++) {
                    float wv = g_Wiu[l * NLOC + m];
                    int nb   = g_iuNbT[l * NLOC + m];
                    float rnb = g_r[nb];
                    acc2 += wv * rnb;
                    atomicAdd(&g_w[nb], -wv * rind);
                    dD -= (double)(wv * rind) * (double)rnb;
                }
                atomicAdd(&g_w[ind2], -acc2);
                dD -= (double)acc2 * (double)rind;
            }
            double2 gd = bred2((double)r_reg * (double)r_reg, dD, sm2);
            if (tid == 0) g_dot1[blockIdx.x] = gd;
        }
        gbar(ep);

        // ---- Phase U: reduce gamma/delta; alpha,beta; update; re-zero w
        {
            double gamma = 0.0, delta = 0.0;
            if (tid < NBLK) {
                double2 gd = g_dot1[tid];
                gamma = gd.x;
                delta = gd.y;
            }
            double2 gd = bred2(gamma, delta, sm2);
            if (tid == 0) {
                gamma = gd.x; delta = gd.y;
                double beta, alpha;
                if (it == 0) {
                    beta = 0.0;
                    alpha = gamma / delta;
                } else {
                    beta = gamma / s_gamma_prev;
                    alpha = gamma / (delta - beta * gamma / s_alpha_prev);
                }
                s_alpha = alpha; s_beta = beta;
                s_gamma_prev = gamma; s_alpha_prev = alpha;
            }
            __syncthreads();
            float alpha = (float)s_alpha;
            float beta  = (float)s_beta;
            float wi = g_w[gtid];
            g_w[gtid] = 0.f;                 // reset accumulator for next iter/replay
            if (it == 0) { p_reg = r_reg; s_reg = wi; }
            else {
                p_reg = r_reg + beta * p_reg;
                s_reg = wi + beta * s_reg;
            }
            x[gtid] += alpha * p_reg;
            r_reg = r_reg - alpha * s_reg;
            g_r[gtid] = r_reg;
        }
        if (it + 1 < CG_STEPS) gbar(ep);
    }
}

// ---------------- host launch ----------------
extern "C" void kernel_launch(void* const* d_in, const int* in_sizes, int n_in,
                              void* d_out, int out_size) {
    const float* CMw    = (const float*)d_in[0];
    const float* LOCw   = (const float*)d_in[1];
    const float* IUw    = (const float*)d_in[2];
    const float* KUw    = (const float*)d_in[3];
    const float* lmbda  = (const float*)d_in[4];
    const float* kToUcf = (const float*)d_in[5];
    const float* known  = (const float*)d_in[6];
    const float* kToU   = (const float*)d_in[7];
    const float* Wd     = (const float*)d_in[8];
    const float* LF     = (const float*)d_in[9];
    const float* IUf    = (const float*)d_in[10];
    const int*   wrow   = (const int*)d_in[11];
    const int*   wcol   = (const int*)d_in[12];
    const int*   locInd = (const int*)d_in[13];
    const int*   iuInd  = (const int*)d_in[14];
    const int*   iuNb   = (const int*)d_in[15];
    float* x = (float*)d_out;

    const int gN   = (NPIX + 255) / 256;
    const int gNNZ = (NNZC + 255) / 256;
    const int gL   = (NLOC + 255) / 256;

    k_z<<<gN, 256>>>();
    k_cnt<<<gNNZ, 256>>>(CMw, Wd, wrow, locInd, iuInd);
    k_scanA<<<432, 1024>>>();
    k_scanB<<<1, 448>>>();
    k_scanC<<<432, 1024>>>();
    k_scatter<<<gNNZ, 256>>>(CMw, Wd, wrow, wcol);
    k_p2<<<gL, 256>>>(LOCw, LF, locInd);
    k_p3<<<gL, 256>>>(IUw, IUf, iuInd, iuNb);
    k_p4<<<gN, 256>>>(KUw, kToUcf, known, kToU, lmbda, x);
    k_cg<<<NBLK, TPB>>>(x);
}

// round 16
// speedup vs baseline: 1.0137x; 1.0137x over previous
#include <cuda_runtime.h>

// ---------------- problem constants (fixed by dataset) ----------------
#define NPIX 147456        // 384*384
#define W384 384
#define NNZC 1474560       // NPIX/2 * 20
#define NLOC 73728         // NPIX/2
#define KIU  5
#define CG_STEPS 30

#define TPB   512
#define NBLK  288          // 288*512 == NPIX exactly
#define MPB   256          // matting pixels per block (NLOC / NBLK)
#define NWARP (TPB / 32)

// ---------------- device scratch (static only) ----------------
__device__ int2  g_pairR[NNZC];        // CSR-sorted {col, val-bits}
__device__ int   g_ptrR[NPIX + 1];
__device__ int   g_ptrM[NPIX];
__device__ int   g_ptrI[NPIX];
__device__ int   g_cntR[NPIX];
__device__ int   g_cntM[NPIX];
__device__ int   g_cntI[NPIX];
__device__ int   g_tmpR[NPIX];
__device__ int   g_tmpM[NPIX];
__device__ int   g_tmpI[NPIX];
__device__ int   g_btot[432];
__device__ int   g_boff[432];

__device__ int   g_mInd[NLOC];         // matting pixel indices, sorted ascending
__device__ int   g_iInd[NLOC];         // IU pixel indices, sorted ascending
__device__ float g_rs_cm[NPIX];
__device__ float g_D[NPIX];
__device__ float g_S45[45 * NLOC];     // symmetric matting blocks [t*NLOC + sorted_pos]
__device__ float g_Wiu[KIU * NLOC];    // [l*NLOC + sorted_pos]
__device__ int   g_iuNbT[KIU * NLOC];  // [l*NLOC + sorted_pos]
__device__ float g_r[NPIX];
__device__ float g_w[NPIX];            // A*r accumulator (atomic; zeroed each iter)
__device__ double2 g_dot1[NBLK];       // {gamma, delta} partials

__device__ unsigned g_count;
__device__ volatile unsigned g_sense;

// ---------------- helpers ----------------
__device__ __forceinline__ int OFF9(int i) {
    int a = i / 3, b = i % 3;
    return (a - 1) + (b - 1) * W384;
}
__device__ __forceinline__ int TIDX(int i, int j) {
    return 9 * i - (i * (i - 1)) / 2 + (j - i);
}

__device__ __forceinline__ double2 bred2(double a, double b, double2* sm2) {
    int lane = threadIdx.x & 31, w = threadIdx.x >> 5;
    #pragma unroll
    for (int o = 16; o > 0; o >>= 1) {
        a += __shfl_down_sync(0xffffffffu, a, o);
        b += __shfl_down_sync(0xffffffffu, b, o);
    }
    if (lane == 0) sm2[w] = make_double2(a, b);
    __syncthreads();
    if (w == 0) {
        double2 t = (lane < NWARP) ? sm2[lane] : make_double2(0.0, 0.0);
        a = t.x; b = t.y;
        #pragma unroll
        for (int o = 8; o > 0; o >>= 1) {
            a += __shfl_down_sync(0xffffu, a, o);
            b += __shfl_down_sync(0xffffu, b, o);
        }
    }
    __syncthreads();
    return make_double2(a, b);
}

__device__ __forceinline__ void gbar(unsigned &ep) {
    ep++;
    __syncthreads();
    if (threadIdx.x == 0) {
        __threadfence();
        if (atomicAdd(&g_count, 1u) == NBLK - 1) {
            g_count = 0;
            __threadfence();
            g_sense = ep;
        } else {
            while (g_sense != ep) { __nanosleep(32); }
            __threadfence();
        }
    }
    __syncthreads();
}

// ---------------- setup kernels ----------------
__global__ void k_z() {
    int i = blockIdx.x * blockDim.x + threadIdx.x;
    if (i < NPIX) {
        g_cntR[i] = 0; g_cntM[i] = 0; g_cntI[i] = 0;
        g_tmpR[i] = 0; g_tmpM[i] = 0; g_tmpI[i] = 0;
        g_rs_cm[i] = 0.f; g_D[i] = 0.f; g_w[i] = 0.f;
    }
    if (i == 0) { g_count = 0; g_sense = 0; }
}

__global__ void k_cnt(const float* __restrict__ CMw, const float* __restrict__ Wd,
                      const int* __restrict__ row,
                      const int* __restrict__ locInd, const int* __restrict__ iuInd) {
    int k = blockIdx.x * blockDim.x + threadIdx.x;
    if (k < NLOC) {
        atomicAdd(&g_cntM[locInd[k]], 1);
        atomicAdd(&g_cntI[iuInd[k]], 1);
    }
    if (k >= NNZC) return;
    int r = row[k];
    float cv = CMw[r] * Wd[k];
    atomicAdd(&g_rs_cm[r], cv);
    atomicAdd(&g_cntR[r], 1);
}

// 432 blocks x 1024: segments of 144 blocks scan cntR / cntM / cntI
__global__ void k_scanA() {
    __shared__ int sm[1024];
    int seg = blockIdx.x / 144;
    int blk = blockIdx.x % 144;
    int gi  = blk * 1024 + threadIdx.x;
    int* cnt = (seg == 0) ? g_cntR : (seg == 1) ? g_cntM : g_cntI;
    int* ptr = (seg == 0) ? g_ptrR : (seg == 1) ? g_ptrM : g_ptrI;
    int v = cnt[gi];
    sm[threadIdx.x] = v;
    __syncthreads();
    for (int o = 1; o < 1024; o <<= 1) {
        int t = (threadIdx.x >= o) ? sm[threadIdx.x - o] : 0;
        __syncthreads();
        sm[threadIdx.x] += t;
        __syncthreads();
    }
    ptr[gi] = sm[threadIdx.x] - v;
    if (threadIdx.x == 1023) g_btot[blockIdx.x] = sm[1023];
}

__global__ void k_scanB() {
    __shared__ int sm[432];
    int t = threadIdx.x;
    int v = (t < 432) ? g_btot[t] : 0;
    if (t < 432) sm[t] = v;
    __syncthreads();
    for (int o = 1; o < 432; o <<= 1) {
        int add = 0;
        if (t < 432 && t >= o) add = sm[t - o];
        __syncthreads();
        if (t < 432) sm[t] += add;
        __syncthreads();
    }
    if (t < 432) {
        int ex = sm[t] - v;
        int seg = t / 144;
        int base = (seg > 0) ? sm[seg * 144 - 1] : 0;
        g_boff[t] = ex - base;
    }
}

__global__ void k_scanC() {
    int seg = blockIdx.x / 144;
    int blk = blockIdx.x % 144;
    int gi  = blk * 1024 + threadIdx.x;
    int* ptr = (seg == 0) ? g_ptrR : (seg == 1) ? g_ptrM : g_ptrI;
    ptr[gi] += g_boff[blockIdx.x];
    if (blockIdx.x == 0 && threadIdx.x == 0) g_ptrR[NPIX] = NNZC;
}

__global__ void k_scatter(const float* __restrict__ CMw, const float* __restrict__ Wd,
                          const int* __restrict__ row, const int* __restrict__ col) {
    int k = blockIdx.x * blockDim.x + threadIdx.x;
    if (k >= NNZC) return;
    int r = row[k], c = col[k];
    int vb = __float_as_int(CMw[r] * Wd[k]);
    int p1 = g_ptrR[r] + atomicAdd(&g_tmpR[r], 1);
    g_pairR[p1] = make_int2(c, vb);
}

// fused prep: data term (NPIX) + matting blocks + IU weights (NLOC), sorted writes
__global__ void k_prep(const float* __restrict__ LOCw, const float* __restrict__ LF,
                       const int* __restrict__ locInd,
                       const float* __restrict__ IUw, const float* __restrict__ IUf,
                       const int* __restrict__ iuInd, const int* __restrict__ nbInd,
                       const float* __restrict__ KUw, const float* __restrict__ kToUconf,
                       const float* __restrict__ known, const float* __restrict__ kToU,
                       const float* __restrict__ lmbda, float* __restrict__ x) {
    int i = blockIdx.x * blockDim.x + threadIdx.x;
    if (i < NPIX) {
        float dk = KUw[i] * kToUconf[i] + lmbda[0] * known[i];
        float b  = dk * kToU[i];
        atomicAdd(&g_D[i], dk);
        g_r[i] = b;     // r0 = b (x0 = 0)
        x[i] = 0.f;
    }
    if (i < NLOC) {
        int m0 = i;
        // matting symmetric blocks at sorted positions
        {
            int ind = locInd[m0];
            int pos = g_ptrM[ind] + atomicAdd(&g_tmpM[ind], 1);
            g_mInd[pos] = ind;
            float w = LOCw[ind];
            float rs[9];
            #pragma unroll
            for (int q = 0; q < 9; q++) rs[q] = 0.f;
            #pragma unroll
            for (int a = 0; a < 9; a++) {
                #pragma unroll
                for (int b2 = a; b2 < 9; b2++) {
                    float s = 0.5f * w * (LF[(b2 * 9 + a) * NLOC + m0] + LF[(a * 9 + b2) * NLOC + m0]);
                    g_S45[TIDX(a, b2) * NLOC + pos] = s;
                    rs[a] += s;
                    if (b2 > a) rs[b2] += s;
                }
            }
            #pragma unroll
            for (int q = 0; q < 9; q++) atomicAdd(&g_D[ind + OFF9(q)], rs[q]);
        }
        // IU weights at sorted positions
        {
            int ind2 = iuInd[m0];
            int pos = g_ptrI[ind2] + atomicAdd(&g_tmpI[ind2], 1);
            g_iInd[pos] = ind2;
            float w = IUw[ind2];
            #pragma unroll
            for (int l = 0; l < KIU; l++) {
                float wv = 0.5f * w * IUf[m0 * KIU + l];
                int nb = nbInd[m0 * KIU + l];
                g_Wiu[l * NLOC + pos] = wv;
                g_iuNbT[l * NLOC + pos] = nb;
                atomicAdd(&g_D[ind2], wv);
                atomicAdd(&g_D[nb], wv);
            }
        }
    }
}

// ---------------- persistent single-reduction CG kernel ----------------
// Per iteration: ONE matvec phase (gather + register-Lv scatter + matting + IU),
// ONE update phase. delta uses r.(A r) = sum(Lv^2) + sum(D r^2) + matting + IU.
__global__ void __launch_bounds__(TPB, 2) k_cg(float* __restrict__ x)
{
    __shared__ double2 sm2[NWARP];
    __shared__ double s_alpha, s_beta, s_gamma_prev, s_alpha_prev;
    const int tid  = threadIdx.x;
    const int gtid = blockIdx.x * TPB + tid;     // always < NPIX
    const int m    = blockIdx.x * MPB + tid;     // sorted matting/IU slot if tid < MPB
    unsigned ep = 0;

    float r_reg = g_r[gtid];
    float p_reg = 0.f, s_reg = 0.f;
    const float rc = g_rs_cm[gtid];
    const float Di = g_D[gtid];
    const int rb0 = g_ptrR[gtid], rb1 = g_ptrR[gtid + 1];

    for (int it = 0; it < CG_STEPS; ++it) {
        // ---- Phase A: full matvec in one phase
        {
            // pass 1: gather r over CSR row -> Lv (register)
            float acc = 0.f;
            int k = rb0;
            for (; k + 4 <= rb1; k += 4) {
                int2 e0 = g_pairR[k],     e1 = g_pairR[k + 1];
                int2 e2 = g_pairR[k + 2], e3 = g_pairR[k + 3];
                acc += __int_as_float(e0.y) * g_r[e0.x]
                     + __int_as_float(e1.y) * g_r[e1.x]
                     + __int_as_float(e2.y) * g_r[e2.x]
                     + __int_as_float(e3.y) * g_r[e3.x];
            }
            for (; k < rb1; k++) {
                int2 e = g_pairR[k];
                acc += __int_as_float(e.y) * g_r[e.x];
            }
            float lv = rc * r_reg - acc;
            float wi = rc * lv + Di * r_reg;
            atomicAdd(&g_w[gtid], wi);
            double dD = (double)lv * (double)lv + (double)(Di * r_reg) * (double)r_reg;

            // pass 2: scatter -val*lv to w[col] (fire-and-forget atomics)
            for (k = rb0; k + 4 <= rb1; k += 4) {
                int2 e0 = g_pairR[k],     e1 = g_pairR[k + 1];
                int2 e2 = g_pairR[k + 2], e3 = g_pairR[k + 3];
                atomicAdd(&g_w[e0.x], -__int_as_float(e0.y) * lv);
                atomicAdd(&g_w[e1.x], -__int_as_float(e1.y) * lv);
                atomicAdd(&g_w[e2.x], -__int_as_float(e2.y) * lv);
                atomicAdd(&g_w[e3.x], -__int_as_float(e3.y) * lv);
            }
            for (; k < rb1; k++) {
                int2 e = g_pairR[k];
                atomicAdd(&g_w[e.x], -__int_as_float(e.y) * lv);
            }

            // matting (sorted; needs only r)
            if (tid < MPB) {
                int ind = g_mInd[m];
                float pn[9], acc9[9];
                #pragma unroll
                for (int j = 0; j < 9; j++) { pn[j] = g_r[ind + OFF9(j)]; acc9[j] = 0.f; }
                #pragma unroll
                for (int i9 = 0; i9 < 9; i9++) {
                    #pragma unroll
                    for (int j9 = i9; j9 < 9; j9++) {
                        float v = g_S45[TIDX(i9, j9) * NLOC + m];
                        acc9[i9] += v * pn[j9];
                        if (j9 > i9) acc9[j9] += v * pn[i9];
                    }
                }
                #pragma unroll
                for (int i9 = 0; i9 < 9; i9++) {
                    atomicAdd(&g_w[ind + OFF9(i9)], -acc9[i9]);
                    dD -= (double)acc9[i9] * (double)pn[i9];
                }
                // IU KNN (sorted by owning pixel)
                int ind2 = g_iInd[m];
                float rind = g_r[ind2];
                float acc2 = 0.f;
                #pragma unroll
                for (int l = 0; l < KIU; l++) {
                    float wv = g_Wiu[l * NLOC + m];
                    int nb   = g_iuNbT[l * NLOC + m];
                    float rnb = g_r[nb];
                    acc2 += wv * rnb;
                    atomicAdd(&g_w[nb], -wv * rind);
                    dD -= (double)(wv * rind) * (double)rnb;
                }
                atomicAdd(&g_w[ind2], -acc2);
                dD -= (double)acc2 * (double)rind;
            }
            double2 gd = bred2((double)r_reg * (double)r_reg, dD, sm2);
            if (tid == 0) g_dot1[blockIdx.x] = gd;
        }
        gbar(ep);

        // ---- Phase U: reduce gamma/delta; alpha,beta; update; exch-zero w
        {
            double gamma = 0.0, delta = 0.0;
            if (tid < NBLK) {
                double2 gd = g_dot1[tid];
                gamma = gd.x;
                delta = gd.y;
            }
            double2 gd = bred2(gamma, delta, sm2);
            if (tid == 0) {
                gamma = gd.x; delta = gd.y;
                double beta, alpha;
                if (it == 0) {
                    beta = 0.0;
                    alpha = gamma / delta;
                } else {
                    beta = gamma / s_gamma_prev;
                    alpha = gamma / (delta - beta * gamma / s_alpha_prev);
                }
                s_alpha = alpha; s_beta = beta;
                s_gamma_prev = gamma; s_alpha_prev = alpha;
            }
            __syncthreads();
            float alpha = (float)s_alpha;
            float beta  = (float)s_beta;
            float wi = atomicExch(&g_w[gtid], 0.f);   // read-and-zero in one op
            if (it == 0) { p_reg = r_reg; s_reg = wi; }
            else {
                p_reg = r_reg + beta * p_reg;
                s_reg = wi + beta * s_reg;
            }
            x[gtid] += alpha * p_reg;
            r_reg = r_reg - alpha * s_reg;
            g_r[gtid] = r_reg;
        }
        if (it + 1 < CG_STEPS) gbar(ep);
    }
}

// ---------------- host launch ----------------
extern "C" void kernel_launch(void* const* d_in, const int* in_sizes, int n_in,
                              void* d_out, int out_size) {
    const float* CMw    = (const float*)d_in[0];
    const float* LOCw   = (const float*)d_in[1];
    const float* IUw    = (const float*)d_in[2];
    const float* KUw    = (const float*)d_in[3];
    const float* lmbda  = (const float*)d_in[4];
    const float* kToUcf = (const float*)d_in[5];
    const float* known  = (const float*)d_in[6];
    const float* kToU   = (const float*)d_in[7];
    const float* Wd     = (const float*)d_in[8];
    const float* LF     = (const float*)d_in[9];
    const float* IUf    = (const float*)d_in[10];
    const int*   wrow   = (const int*)d_in[11];
    const int*   wcol   = (const int*)d_in[12];
    const int*   locInd = (const int*)d_in[13];
    const int*   iuInd  = (const int*)d_in[14];
    const int*   iuNb   = (const int*)d_in[15];
    float* x = (float*)d_out;

    const int gN   = (NPIX + 255) / 256;
    const int gNNZ = (NNZC + 255) / 256;

    k_z<<<gN, 256>>>();
    k_cnt<<<gNNZ, 256>>>(CMw, Wd, wrow, locInd, iuInd);
    k_scanA<<<432, 1024>>>();
    k_scanB<<<1, 448>>>();
    k_scanC<<<432, 1024>>>();
    k_scatter<<<gNNZ, 256>>>(CMw, Wd, wrow, wcol);
    k_prep<<<gN, 256>>>(LOCw, LF, locInd, IUw, IUf, iuInd, iuNb,
                        KUw, kToUcf, known, kToU, lmbda, x);
    k_cg<<<NBLK, TPB>>>(x);
}